// round 11
// baseline (speedup 1.0000x reference)
#include <cuda_runtime.h>
#include <cstdint>

#define BATCH 256
#define DIM   2048
#define PNUM  56
#define NC    4                        // chunks per block
#define RPAD  132                      // floats per smem row (33 float4)
#define GRID1 (BATCH * 4)              // 1024 blocks: (b, o)

// smem layout (floats)
#define S_P0   0                       // 56 x 132
#define S_P1   (56 * RPAD)             // 7392
#define S_M    (2 * 56 * RPAD)         // 14784: mean, 128 floats
#define S_MG   (S_M + 128)             // m - g, 128 floats
#define S_RED  (S_MG + 128)            // 1024 floats (mean partials / dcl fold)
#define SMEMF  (S_RED + 1024)          // 16064 floats = 64256 bytes

#define KEXP  0.3606737602222409f

typedef unsigned long long u64;

// --- device scratch ---
__device__ double       g_acc0;                 // dil
__device__ double       g_acc1;                 // dcl
__device__ unsigned int g_done;
__device__ float4       scr_dcl[GRID1 * 56];    // per (b,o): 56 row partials
__device__ float4       scr_dil[GRID1];         // per (b,o): dil partial

__device__ __forceinline__ float ex2f(float x) {
    float r; asm("ex2.approx.ftz.f32 %0, %1;" : "=f"(r) : "f"(x)); return r;
}
__device__ __forceinline__ u64 f2_add(u64 a, u64 b) {
    u64 r; asm("add.rn.f32x2 %0, %1, %2;" : "=l"(r) : "l"(a), "l"(b)); return r;
}
__device__ __forceinline__ u64 f2_mul(u64 a, u64 b) {
    u64 r; asm("mul.rn.f32x2 %0, %1, %2;" : "=l"(r) : "l"(a), "l"(b)); return r;
}
__device__ __forceinline__ u64 f2_fma(u64 a, u64 b, u64 c) {
    u64 r; asm("fma.rn.f32x2 %0, %1, %2, %3;" : "=l"(r) : "l"(a), "l"(b), "l"(c)); return r;
}
__device__ __forceinline__ void f2_unpack(u64 v, float& lo, float& hi) {
    asm("mov.b64 {%0, %1}, %2;" : "=f"(lo), "=f"(hi) : "l"(v));
}
__device__ __forceinline__ u64 f2_pack(float lo, float hi) {
    u64 r; asm("mov.b64 %0, {%1, %2};" : "=l"(r) : "f"(lo), "f"(hi)); return r;
}
__device__ __forceinline__ void cpa16(uint32_t s, const void* g) {
    asm volatile("cp.async.cg.shared.global [%0], [%1], 16;" :: "r"(s), "l"(g));
}

#define F2_NEG1 0xBF800000BF800000ULL
#define F2_KK   0x3EB8AA3B3EB8AA3BULL   /* (KEXP, KEXP) */
#define F2_I56  0x3C9249253C924925ULL   /* (1/56, 1/56) */

// ============================================================================
// k1: block = (b, o). Pipelined over 4 chunks of 128 cols:
//   prefetch c+1 (cp.async) -> compute mean/dil/dcl on c from smem.
// dcl/dil accumulators persist in registers across chunks.
// ============================================================================
__global__ void __launch_bounds__(256, 3) k1(const float* __restrict__ ebp,
                                             const float* __restrict__ ebg) {
    extern __shared__ float sm[];
    int bo = blockIdx.x;
    int b  = bo >> 2;
    int o  = bo & 3;
    int tid = threadIdx.x;

    if (bo == 0 && tid == 0) { g_acc0 = 0.0; g_acc1 = 0.0; g_done = 0u; }

    const float4* ebp4 = (const float4*)ebp;
    uint32_t sbase = (uint32_t)__cvta_generic_to_shared(sm);

    // issue one chunk load: 56 rows x 32 float4, 7 cp.async per thread
#define ISSUE(c, buf) {                                                       \
        size_t gc = (size_t)((o * 4 + (c)) * 32);                             \
        uint32_t sb = sbase + ((buf) ? S_P1 : S_P0) * 4;                      \
        _Pragma("unroll")                                                     \
        for (int i = 0; i < 7; i++) {                                         \
            int idx = tid + 256 * i;                                          \
            int row = idx >> 5, col = idx & 31;                               \
            cpa16(sb + (uint32_t)(row * RPAD + col * 4) * 4,                  \
                  ebp4 + (size_t)(row * BATCH + b) * 512 + gc + col);         \
        }                                                                     \
        asm volatile("cp.async.commit_group;"); }

    ISSUE(0, 0)

    // persistent accumulators
    u64 seX = 0, seY = 0, suX = 0, suY = 0;             // dcl (tid<224)
    float dse_g = 0.f, dse_m = 0.f, dsu_g = 0.f, dsu_m = 0.f;  // dil (tid<32)

    int s = tid / 56, r = tid - s * 56;   // phase C mapping
    int mcol = tid & 31, mrg = tid >> 5;  // mean mapping

    for (int c = 0; c < NC; c++) {
        float* P = sm + ((c & 1) ? S_P1 : S_P0);
        if (c + 1 < NC) {
            if ((c + 1) & 1) { ISSUE(c + 1, 1) } else { ISSUE(c + 1, 0) }
            asm volatile("cp.async.wait_group 1;");
        } else {
            asm volatile("cp.async.wait_group 0;");
        }
        __syncthreads();

        // ---- mean partials: rows mrg*7 .. mrg*7+6, col mcol ----
        {
            u64 aLo = 0, aHi = 0;
#pragma unroll 7
            for (int k = 0; k < 7; k++) {
                ulonglong2 v = *(ulonglong2*)&P[(mrg * 7 + k) * RPAD + mcol * 4];
                aLo = f2_add(aLo, v.x); aHi = f2_add(aHi, v.y);
            }
            *(ulonglong2*)&sm[S_RED + (mrg * 32 + mcol) * 4] = make_ulonglong2(aLo, aHi);
        }
        __syncthreads();

        // ---- fold mean, compute mg, dil accum (threads 0..31) ----
        if (tid < 32) {
            u64 mLo = 0, mHi = 0;
#pragma unroll 8
            for (int k = 0; k < 8; k++) {
                ulonglong2 v = *(ulonglong2*)&sm[S_RED + (k * 32 + tid) * 4];
                mLo = f2_add(mLo, v.x); mHi = f2_add(mHi, v.y);
            }
            mLo = f2_mul(mLo, F2_I56); mHi = f2_mul(mHi, F2_I56);
            float4 g = ((const float4*)(ebg + (size_t)b * DIM))[(o * 4 + c) * 32 + tid];
            u64 gLo = f2_pack(g.x, g.y), gHi = f2_pack(g.z, g.w);
            u64 mgLo = f2_fma(gLo, F2_NEG1, mLo);
            u64 mgHi = f2_fma(gHi, F2_NEG1, mHi);
            *(ulonglong2*)&sm[S_M  + tid * 4] = make_ulonglong2(mLo, mHi);
            *(ulonglong2*)&sm[S_MG + tid * 4] = make_ulonglong2(mgLo, mgHi);

            float m0, m1, m2, m3, u0, u1, u2, u3;
            f2_unpack(mLo, m0, m1); f2_unpack(mHi, m2, m3);
            f2_unpack(mgLo, u0, u1); f2_unpack(mgHi, u2, u3);
#define DIL1(gg, mm, uu) { float eg = ex2f(gg * KEXP);          \
                           float em = ex2f(mm * KEXP);          \
                           dse_g += eg; dse_m += em;            \
                           dsu_g = fmaf(eg, uu, dsu_g);         \
                           dsu_m = fmaf(em, uu, dsu_m); }
            DIL1(g.x, m0, u0) DIL1(g.y, m1, u1) DIL1(g.z, m2, u2) DIL1(g.w, m3, u3)
#undef DIL1
        }
        __syncthreads();

        // ---- phase C: dcl accumulate (tid<224) ----
        if (s < 4) {
            int j0 = s * 8;
#pragma unroll 8
            for (int j = 0; j < 8; j++) {
                ulonglong2 Pv = *(ulonglong2*)&P[r * RPAD + (j0 + j) * 4];
                ulonglong2 M  = *(ulonglong2*)&sm[S_M  + (j0 + j) * 4];
                ulonglong2 MG = *(ulonglong2*)&sm[S_MG + (j0 + j) * 4];
#define DCLP(pp, mm, gm) {                                       \
                u64 db = f2_fma(pp, F2_NEG1, mm);                \
                u64 dg = f2_fma(gm, F2_NEG1, db);                \
                u64 w  = f2_add(db, dg);                         \
                u64 u  = f2_mul(gm, w);                          \
                u64 ax = f2_mul(f2_mul(dg, dg), F2_KK);          \
                u64 ay = f2_mul(f2_mul(db, db), F2_KK);          \
                float a0, a1, b0, b1;                            \
                f2_unpack(ax, a0, a1); f2_unpack(ay, b0, b1);    \
                u64 ex = f2_pack(ex2f(a0), ex2f(a1));            \
                u64 ey = f2_pack(ex2f(b0), ex2f(b1));            \
                seX = f2_add(seX, ex); seY = f2_add(seY, ey);    \
                suX = f2_fma(ex, u, suX); suY = f2_fma(ey, u, suY); }
                DCLP(Pv.x, M.x, MG.x)
                DCLP(Pv.y, M.y, MG.y)
#undef DCLP
            }
        }
        __syncthreads();
    }

    // ---- write dcl partials to smem, dil reduce ----
    if (s < 4) {
        float x0, x1, y0, y1, z0, z1, w0, w1;
        f2_unpack(seX, x0, x1); f2_unpack(seY, y0, y1);
        f2_unpack(suX, z0, z1); f2_unpack(suY, w0, w1);
        *(float4*)&sm[S_RED + (s * 56 + r) * 4] =
            make_float4(x0 + x1, y0 + y1, z0 + z1, w0 + w1);
    }
    if (tid < 32) {
#pragma unroll
        for (int off = 16; off; off >>= 1) {
            dse_g += __shfl_xor_sync(0xffffffffu, dse_g, off);
            dse_m += __shfl_xor_sync(0xffffffffu, dse_m, off);
            dsu_g += __shfl_xor_sync(0xffffffffu, dsu_g, off);
            dsu_m += __shfl_xor_sync(0xffffffffu, dsu_m, off);
        }
        if (tid == 0) scr_dil[bo] = make_float4(dse_g, dse_m, dsu_g, dsu_m);
    }
    __syncthreads();
    if (tid < 56) {
        float4 a = *(float4*)&sm[S_RED + (0 * 56 + tid) * 4];
        float4 c = *(float4*)&sm[S_RED + (1 * 56 + tid) * 4];
        float4 d = *(float4*)&sm[S_RED + (2 * 56 + tid) * 4];
        float4 e = *(float4*)&sm[S_RED + (3 * 56 + tid) * 4];
        scr_dcl[bo * 56 + tid] =
            make_float4(a.x + c.x + d.x + e.x, a.y + c.y + d.y + e.y,
                        a.z + c.z + d.z + e.z, a.w + c.w + d.w + e.w);
    }
}

// ============================================================================
// k2: 256 blocks, one per b. tid<56: fold 4 o-partials per row, divide,
// block-reduce -> dcl atomic. Warp 7: dil fold -> dil atomic. Last block -> out.
// ============================================================================
__global__ void __launch_bounds__(256) k2(float* __restrict__ out) {
    __shared__ float sdcl[56];
    __shared__ int s_last;
    int b = blockIdx.x;
    int tid = threadIdx.x, lane = tid & 31;

    if (tid < 56) {
        float4 a = make_float4(0.f, 0.f, 0.f, 0.f);
#pragma unroll 4
        for (int oo = 0; oo < 4; oo++) {
            float4 v = scr_dcl[(b * 4 + oo) * 56 + tid];
            a.x += v.x; a.y += v.y; a.z += v.z; a.w += v.w;
        }
        sdcl[tid] = a.w / a.y - a.z / a.x;
    }
    if (tid >= 224) {                   // warp 7: dil fold for this b
        float4 v = (lane < 4) ? scr_dil[b * 4 + lane]
                              : make_float4(0.f, 0.f, 0.f, 0.f);
#pragma unroll
        for (int off = 2; off; off >>= 1) {
            v.x += __shfl_xor_sync(0xffffffffu, v.x, off);
            v.y += __shfl_xor_sync(0xffffffffu, v.y, off);
            v.z += __shfl_xor_sync(0xffffffffu, v.z, off);
            v.w += __shfl_xor_sync(0xffffffffu, v.w, off);
        }
        if (lane == 0)
            atomicAdd(&g_acc0, (double)(v.w / v.y - v.z / v.x));
    }
    __syncthreads();
    if (tid < 32) {
        float ss = ((lane < 56) ? sdcl[lane] : 0.f) +
                   ((lane + 32 < 56) ? sdcl[lane + 32] : 0.f);
#pragma unroll
        for (int off = 16; off; off >>= 1)
            ss += __shfl_xor_sync(0xffffffffu, ss, off);
        if (lane == 0) atomicAdd(&g_acc1, (double)ss);
    }

    __threadfence();
    __syncthreads();
    if (tid == 0) {
        unsigned prev = atomicAdd(&g_done, 1u);
        s_last = (prev == gridDim.x - 1) ? 1 : 0;
    }
    __syncthreads();
    if (s_last && tid == 0) {
        __threadfence();
        double a0 = *(volatile double*)&g_acc0;
        double a1 = *(volatile double*)&g_acc1;
        out[0] = (float)(a0 * (4.0 / (double)DIM));
        out[1] = (float)(a1 * (4.0 / ((double)DIM * (double)PNUM)));
    }
}

extern "C" void kernel_launch(void* const* d_in, const int* in_sizes, int n_in,
                              void* d_out, int out_size) {
    const float* ebg = (const float*)d_in[0];
    const float* ebp = (const float*)d_in[1];
    (void)in_sizes; (void)n_in; (void)out_size;

    cudaFuncSetAttribute(k1, cudaFuncAttributeMaxDynamicSharedMemorySize,
                         SMEMF * sizeof(float));
    k1<<<GRID1, 256, SMEMF * sizeof(float)>>>(ebp, ebg);
    k2<<<BATCH, 256>>>((float*)d_out);
}

// round 12
// speedup vs baseline: 1.1168x; 1.1168x over previous
#include <cuda_runtime.h>
#include <cstdint>

#define BATCH 256
#define DIM   2048
#define PNUM  56
#define CH    16                       // 128-col chunks per batch row
#define GRID1 (BATCH * CH)             // 4096

// smem layout (floats)
#define S_P    0                       // 56 x 132 (128 cols + 4 pad)
#define RPAD   132
#define S_M    (56 * RPAD)             // 7392: mean, 128 floats
#define S_MG   (S_M + 128)             // m - g, 128 floats
#define S_RED  (S_MG + 128)            // 8 x 128 mean partials / dcl fold (1024)
#define SMEMF  (S_RED + 1024)          // 8672 floats = 34688 bytes

#define KEXP  0.3606737602222409f

typedef unsigned long long u64;

// --- device scratch ---
__device__ double       g_acc0;                 // dil
__device__ double       g_acc1;                 // dcl
__device__ unsigned int g_done;
__device__ float4       scr_dcl[GRID1 * 56];    // per (b,ch): 56 row partials
__device__ float4       scr_dil[GRID1];         // per (b,ch): 1 dil partial

__device__ __forceinline__ float ex2f(float x) {
    float r; asm("ex2.approx.ftz.f32 %0, %1;" : "=f"(r) : "f"(x)); return r;
}
__device__ __forceinline__ u64 f2_add(u64 a, u64 b) {
    u64 r; asm("add.rn.f32x2 %0, %1, %2;" : "=l"(r) : "l"(a), "l"(b)); return r;
}
__device__ __forceinline__ u64 f2_mul(u64 a, u64 b) {
    u64 r; asm("mul.rn.f32x2 %0, %1, %2;" : "=l"(r) : "l"(a), "l"(b)); return r;
}
__device__ __forceinline__ u64 f2_fma(u64 a, u64 b, u64 c) {
    u64 r; asm("fma.rn.f32x2 %0, %1, %2, %3;" : "=l"(r) : "l"(a), "l"(b), "l"(c)); return r;
}
__device__ __forceinline__ void f2_unpack(u64 v, float& lo, float& hi) {
    asm("mov.b64 {%0, %1}, %2;" : "=f"(lo), "=f"(hi) : "l"(v));
}
__device__ __forceinline__ u64 f2_pack(float lo, float hi) {
    u64 r; asm("mov.b64 %0, {%1, %2};" : "=l"(r) : "f"(lo), "f"(hi)); return r;
}

#define F2_NEG1 0xBF800000BF800000ULL
#define F2_KK   0x3EB8AA3B3EB8AA3BULL   /* (KEXP, KEXP) */
#define F2_I56  0x3C9249253C924925ULL   /* (1/56, 1/56) */

// ============================================================================
// k1: block = (b, 128-col chunk). A: load 56 rows -> smem + mean partials.
// Mid: fold mean, mg, dil partial. C: thread=(row,subchunk of 32 cols) dcl
// partials -> smem; fold 4 -> 56 float4 -> scratch.
// ============================================================================
__global__ void __launch_bounds__(256, 5) k1(const float* __restrict__ ebp,
                                             const float* __restrict__ ebg) {
    extern __shared__ float sm[];
    int bo = blockIdx.x;
    int b  = bo >> 4;
    int ch = bo & 15;
    int tid = threadIdx.x;

    if (bo == 0 && tid == 0) { g_acc0 = 0.0; g_acc1 = 0.0; g_done = 0u; }

    // ---- Phase A: load 56 x 32 float4 + mean partials ----
    int rg = tid >> 5;          // 0..7, handles rows rg, rg+8, ..., rg+48
    int c4 = tid & 31;          // float4 index in chunk
    const ulonglong2* eb = (const ulonglong2*)ebp;
    size_t coff = (size_t)ch * 32 + c4;
    u64 aLo = 0, aHi = 0;
#pragma unroll 7
    for (int i = 0; i < 7; i++) {
        int p = i * 8 + rg;
        ulonglong2 v = eb[(size_t)(p * BATCH + b) * 512 + coff];
        *(ulonglong2*)&sm[S_P + p * RPAD + c4 * 4] = v;
        aLo = f2_add(aLo, v.x);
        aHi = f2_add(aHi, v.y);
    }
    *(ulonglong2*)&sm[S_RED + rg * 128 + c4 * 4] = make_ulonglong2(aLo, aHi);
    __syncthreads();

    // ---- Mid: fold mean, mg, dil partial (threads 0..31) ----
    if (tid < 32) {
        u64 mLo = 0, mHi = 0;
#pragma unroll 8
        for (int k = 0; k < 8; k++) {
            ulonglong2 v = *(ulonglong2*)&sm[S_RED + k * 128 + tid * 4];
            mLo = f2_add(mLo, v.x); mHi = f2_add(mHi, v.y);
        }
        mLo = f2_mul(mLo, F2_I56); mHi = f2_mul(mHi, F2_I56);
        ulonglong2 g = ((const ulonglong2*)ebg)[(size_t)b * 512 + coff];
        u64 mgLo = f2_fma(g.x, F2_NEG1, mLo);
        u64 mgHi = f2_fma(g.y, F2_NEG1, mHi);
        *(ulonglong2*)&sm[S_M  + tid * 4] = make_ulonglong2(mLo, mHi);
        *(ulonglong2*)&sm[S_MG + tid * 4] = make_ulonglong2(mgLo, mgHi);

        float m0, m1, m2, m3, g0, g1, g2, g3, u0, u1, u2, u3;
        f2_unpack(mLo, m0, m1); f2_unpack(mHi, m2, m3);
        f2_unpack(g.x, g0, g1); f2_unpack(g.y, g2, g3);
        f2_unpack(mgLo, u0, u1); f2_unpack(mgHi, u2, u3);
        float se_g = 0.f, se_m = 0.f, su_g = 0.f, su_m = 0.f;
#define DIL1(gg, mm, uu) { float eg = ex2f(gg * KEXP);          \
                           float em = ex2f(mm * KEXP);          \
                           se_g += eg; se_m += em;              \
                           su_g = fmaf(eg, uu, su_g);           \
                           su_m = fmaf(em, uu, su_m); }
        DIL1(g0, m0, u0) DIL1(g1, m1, u1) DIL1(g2, m2, u2) DIL1(g3, m3, u3)
#undef DIL1
#pragma unroll
        for (int off = 16; off; off >>= 1) {
            se_g += __shfl_xor_sync(0xffffffffu, se_g, off);
            se_m += __shfl_xor_sync(0xffffffffu, se_m, off);
            su_g += __shfl_xor_sync(0xffffffffu, su_g, off);
            su_m += __shfl_xor_sync(0xffffffffu, su_m, off);
        }
        if (tid == 0)
            scr_dil[bo] = make_float4(se_g, se_m, su_g, su_m);
    }
    __syncthreads();

    // ---- Phase C: per-thread dcl partials (tid < 224) ----
    int s = tid / 56;                  // subchunk 0..3
    int r = tid - s * 56;              // row 0..55
    if (s < 4) {
        int j0 = s * 8;
        u64 seX = 0, seY = 0, suX = 0, suY = 0;
#pragma unroll 8
        for (int j = 0; j < 8; j++) {
            ulonglong2 P  = *(ulonglong2*)&sm[S_P  + r * RPAD + (j0 + j) * 4];
            ulonglong2 M  = *(ulonglong2*)&sm[S_M  + (j0 + j) * 4];
            ulonglong2 MG = *(ulonglong2*)&sm[S_MG + (j0 + j) * 4];
#define DCLP(pp, mm, gm) {                                       \
            u64 db = f2_fma(pp, F2_NEG1, mm);    /* m - p */     \
            u64 dg = f2_fma(gm, F2_NEG1, db);    /* g - p */     \
            u64 w  = f2_add(db, dg);                             \
            u64 u  = f2_mul(gm, w);                              \
            u64 ax = f2_mul(f2_mul(dg, dg), F2_KK);              \
            u64 ay = f2_mul(f2_mul(db, db), F2_KK);              \
            float a0, a1, b0, b1;                                \
            f2_unpack(ax, a0, a1); f2_unpack(ay, b0, b1);        \
            u64 ex = f2_pack(ex2f(a0), ex2f(a1));                \
            u64 ey = f2_pack(ex2f(b0), ex2f(b1));                \
            seX = f2_add(seX, ex); seY = f2_add(seY, ey);        \
            suX = f2_fma(ex, u, suX); suY = f2_fma(ey, u, suY); }
            DCLP(P.x, M.x, MG.x)
            DCLP(P.y, M.y, MG.y)
#undef DCLP
        }
        float x0, x1, y0, y1, z0, z1, w0, w1;
        f2_unpack(seX, x0, x1); f2_unpack(seY, y0, y1);
        f2_unpack(suX, z0, z1); f2_unpack(suY, w0, w1);
        *(float4*)&sm[S_RED + (s * 56 + r) * 4] =
            make_float4(x0 + x1, y0 + y1, z0 + z1, w0 + w1);
    }
    __syncthreads();

    // ---- fold 4 subchunks -> 1 float4 per row ----
    if (tid < 56) {
        float4 a = *(float4*)&sm[S_RED + (0 * 56 + tid) * 4];
        float4 c = *(float4*)&sm[S_RED + (1 * 56 + tid) * 4];
        float4 d = *(float4*)&sm[S_RED + (2 * 56 + tid) * 4];
        float4 e = *(float4*)&sm[S_RED + (3 * 56 + tid) * 4];
        scr_dcl[bo * 56 + tid] =
            make_float4(a.x + c.x + d.x + e.x, a.y + c.y + d.y + e.y,
                        a.z + c.z + d.z + e.z, a.w + c.w + d.w + e.w);
    }
}

// ============================================================================
// k2: 256 blocks, one per b. tid<56: fold 16 chunk-partials per row, divide,
// block-reduce -> dcl atomic. Warp 7: dil fold -> dil atomic. Last block -> out.
// ============================================================================
__global__ void __launch_bounds__(256) k2(float* __restrict__ out) {
    __shared__ float sdcl[56];
    __shared__ int s_last;
    int b = blockIdx.x;
    int tid = threadIdx.x, lane = tid & 31;

    if (tid < 56) {
        float4 a = make_float4(0.f, 0.f, 0.f, 0.f);
#pragma unroll 16
        for (int cc = 0; cc < CH; cc++) {
            float4 v = scr_dcl[(b * CH + cc) * 56 + tid];
            a.x += v.x; a.y += v.y; a.z += v.z; a.w += v.w;
        }
        sdcl[tid] = a.w / a.y - a.z / a.x;
    }
    if (tid >= 224) {                   // warp 7: dil fold for this b
        float4 v = (lane < 16) ? scr_dil[b * 16 + lane]
                               : make_float4(0.f, 0.f, 0.f, 0.f);
#pragma unroll
        for (int off = 8; off; off >>= 1) {
            v.x += __shfl_xor_sync(0xffffffffu, v.x, off);
            v.y += __shfl_xor_sync(0xffffffffu, v.y, off);
            v.z += __shfl_xor_sync(0xffffffffu, v.z, off);
            v.w += __shfl_xor_sync(0xffffffffu, v.w, off);
        }
        if (lane == 0)
            atomicAdd(&g_acc0, (double)(v.w / v.y - v.z / v.x));
    }
    __syncthreads();
    if (tid < 32) {
        float ss = ((lane < 56) ? sdcl[lane] : 0.f) +
                   ((lane + 32 < 56) ? sdcl[lane + 32] : 0.f);
#pragma unroll
        for (int off = 16; off; off >>= 1)
            ss += __shfl_xor_sync(0xffffffffu, ss, off);
        if (lane == 0) atomicAdd(&g_acc1, (double)ss);
    }

    __threadfence();
    __syncthreads();
    if (tid == 0) {
        unsigned prev = atomicAdd(&g_done, 1u);
        s_last = (prev == gridDim.x - 1) ? 1 : 0;
    }
    __syncthreads();
    if (s_last && tid == 0) {
        __threadfence();
        double a0 = *(volatile double*)&g_acc0;
        double a1 = *(volatile double*)&g_acc1;
        out[0] = (float)(a0 * (4.0 / (double)DIM));
        out[1] = (float)(a1 * (4.0 / ((double)DIM * (double)PNUM)));
    }
}

extern "C" void kernel_launch(void* const* d_in, const int* in_sizes, int n_in,
                              void* d_out, int out_size) {
    const float* ebg = (const float*)d_in[0];
    const float* ebp = (const float*)d_in[1];
    (void)in_sizes; (void)n_in; (void)out_size;

    cudaFuncSetAttribute(k1, cudaFuncAttributeMaxDynamicSharedMemorySize,
                         SMEMF * sizeof(float));
    k1<<<GRID1, 256, SMEMF * sizeof(float)>>>(ebp, ebg);
    k2<<<BATCH, 256>>>((float*)d_out);
}